// round 1
// baseline (speedup 1.0000x reference)
#include <cuda_runtime.h>
#include <math.h>

// ---------------- problem constants ----------------
#define Bc   2
#define Sc   2048
#define Ec   2048
#define Hc   64
#define Pc   64
#define Nc   128
#define Kc   4
#define CHc  256
#define NCHc 8
#define INTERc 4096
#define CONVDc 4352
#define PROJc  8512
#define ROWSc  4096          // B*S
#define EPSc   1e-5f

// ---------------- scratch (static device globals; no allocation) -------------
__device__ float g_proj[(size_t)ROWSc * PROJc];     // [B,S,PROJ]
__device__ float g_xbc [(size_t)ROWSc * CONVDc];    // conv+silu output [B,S,CONV_DIM]
__device__ float g_dt  [ROWSc * Hc];                // softplus dt
__device__ float g_acum[Bc * Hc * NCHc * CHc];      // per-chunk inclusive cumsum of A*dt
__device__ float g_suma[Bc * Hc * NCHc];            // chunk total
__device__ float g_states[(size_t)Bc * NCHc * Hc * Pc * Nc]; // local then prev states
__device__ float g_y   [(size_t)ROWSc * INTERc];    // Y (diag + off + D*x), then normed

// ============================================================================
// SGEMM:  C[M,Ncols] = A[M,Kd] * Bw[Ncols,Kd]^T   (both row-major, K contiguous)
// 128x128 block tile, BK=16, 256 threads, 8x8 per thread.
// ============================================================================
__global__ __launch_bounds__(256) void sgemm_nt(
    const float* __restrict__ A, const float* __restrict__ Bw,
    float* __restrict__ C, int M, int Ncols, int Kd)
{
    __shared__ float As[16][128];
    __shared__ float Bs[16][128];
    const int tid = threadIdx.x;
    const int bm = blockIdx.y * 128;
    const int bn = blockIdx.x * 128;
    const int tm = (tid >> 4) << 3;
    const int tn = (tid & 15) << 3;

    float acc[8][8];
#pragma unroll
    for (int i = 0; i < 8; i++)
#pragma unroll
        for (int j = 0; j < 8; j++) acc[i][j] = 0.f;

    for (int k0 = 0; k0 < Kd; k0 += 16) {
#pragma unroll
        for (int f = tid; f < 512; f += 256) {
            int row = f >> 2;
            int kk  = (f & 3) << 2;
            float4 v = *(const float4*)(A + (size_t)(bm + row) * Kd + k0 + kk);
            As[kk+0][row] = v.x; As[kk+1][row] = v.y;
            As[kk+2][row] = v.z; As[kk+3][row] = v.w;
        }
#pragma unroll
        for (int f = tid; f < 512; f += 256) {
            int row = f >> 2;
            int kk  = (f & 3) << 2;
            float4 v = make_float4(0.f, 0.f, 0.f, 0.f);
            if (bn + row < Ncols)
                v = *(const float4*)(Bw + (size_t)(bn + row) * Kd + k0 + kk);
            Bs[kk+0][row] = v.x; Bs[kk+1][row] = v.y;
            Bs[kk+2][row] = v.z; Bs[kk+3][row] = v.w;
        }
        __syncthreads();
#pragma unroll
        for (int kk = 0; kk < 16; kk++) {
            float4 a0 = *(const float4*)&As[kk][tm];
            float4 a1 = *(const float4*)&As[kk][tm + 4];
            float4 b0 = *(const float4*)&Bs[kk][tn];
            float4 b1 = *(const float4*)&Bs[kk][tn + 4];
            float a[8] = {a0.x,a0.y,a0.z,a0.w,a1.x,a1.y,a1.z,a1.w};
            float b[8] = {b0.x,b0.y,b0.z,b0.w,b1.x,b1.y,b1.z,b1.w};
#pragma unroll
            for (int i = 0; i < 8; i++)
#pragma unroll
                for (int j = 0; j < 8; j++) acc[i][j] += a[i]*b[j];
        }
        __syncthreads();
    }
#pragma unroll
    for (int i = 0; i < 8; i++) {
        int row = bm + tm + i;
#pragma unroll
        for (int j = 0; j < 8; j += 4) {
            int col = bn + tn + j;
            if (col < Ncols) {
                float4 v = make_float4(acc[i][j], acc[i][j+1], acc[i][j+2], acc[i][j+3]);
                *(float4*)(C + (size_t)row * Ncols + col) = v;
            }
        }
    }
}

// ============================================================================
// Depthwise causal conv (K=4) + bias + SiLU over the hBC slice of proj.
// One thread per channel, register sliding window over S. Coalesced in c.
// ============================================================================
__global__ __launch_bounds__(256) void conv_silu_kernel(
    const float* __restrict__ proj, const float* __restrict__ conv_w,
    const float* __restrict__ conv_b, float* __restrict__ xbc)
{
    int c = blockIdx.x * blockDim.x + threadIdx.x;   // [0, CONV_DIM)
    int b = blockIdx.y;
    if (c >= CONVDc) return;
    float w0 = conv_w[c*Kc+0], w1 = conv_w[c*Kc+1];
    float w2 = conv_w[c*Kc+2], w3 = conv_w[c*Kc+3];
    float bias = conv_b[c];
    const float* src = proj + (size_t)b * Sc * PROJc + INTERc + c;
    float* dst = xbc + (size_t)b * Sc * CONVDc + c;
    float x0 = 0.f, x1 = 0.f, x2 = 0.f;
    for (int s = 0; s < Sc; s++) {
        float x3 = src[(size_t)s * PROJc];
        float v  = w0*x0 + w1*x1 + w2*x2 + w3*x3 + bias;
        v = v / (1.f + expf(-v));                     // SiLU
        dst[(size_t)s * CONVDc] = v;
        x0 = x1; x1 = x2; x2 = x3;
    }
}

// ============================================================================
// dt = softplus(dt_raw + bias); Adt = -exp(A_log)*dt; per-chunk inclusive scan.
// One block (256 threads = CH) per (b, c, h).
// ============================================================================
__global__ __launch_bounds__(256) void dt_scan_kernel(
    const float* __restrict__ proj, const float* __restrict__ A_log,
    const float* __restrict__ dt_bias, float* __restrict__ dt_out,
    float* __restrict__ acum, float* __restrict__ suma)
{
    int h = blockIdx.x, c = blockIdx.y, b = blockIdx.z;
    int l = threadIdx.x;
    int s = c * CHc + l;
    float raw = proj[(size_t)(b*Sc + s)*PROJc + INTERc + CONVDc + h] + dt_bias[h];
    float sp  = (raw > 20.f) ? raw : log1pf(expf(raw));
    dt_out[(size_t)(b*Sc + s)*Hc + h] = sp;
    float a = -expf(A_log[h]) * sp;

    __shared__ float sb[CHc];
    sb[l] = a;
    __syncthreads();
    for (int off = 1; off < CHc; off <<= 1) {
        float t = (l >= off) ? sb[l - off] : 0.f;
        __syncthreads();
        sb[l] += t;
        __syncthreads();
    }
    acum[((size_t)(b*Hc + h)*NCHc + c)*CHc + l] = sb[l];
    if (l == CHc - 1) suma[(b*Hc + h)*NCHc + c] = sb[l];
}

// ============================================================================
// Local chunk state:  S[p,n] = sum_s x[s,p]*dt[s]*exp(sumA-Acum[s]) * B[s,n]
// One block per (b,c,h). smem tiles of 64 rows. acc: 4p x 8n per thread.
// ============================================================================
#define LS_SMEM ((64*68 + 64*132) * 4)
__global__ __launch_bounds__(256) void local_state_kernel(
    const float* __restrict__ xbc, const float* __restrict__ dt,
    const float* __restrict__ acum, float* __restrict__ states)
{
    int h = blockIdx.x, c = blockIdx.y, b = blockIdx.z;
    extern __shared__ float sm0[];
    float* sXd = sm0;              // [64][68]  x*dt*decay
    float* sB  = sm0 + 64*68;      // [64][132] B rows
    __shared__ float sAcum[CHc];

    int tid = threadIdx.x;
    size_t abase = ((size_t)(b*Hc + h)*NCHc + c)*CHc;
    for (int i = tid; i < CHc; i += 256) sAcum[i] = acum[abase + i];
    __syncthreads();
    float sumA = sAcum[CHc - 1];

    int tr = tid >> 4, tc = tid & 15;      // p-tile, n-tile
    float acc[4][8];
#pragma unroll
    for (int i = 0; i < 4; i++)
#pragma unroll
        for (int j = 0; j < 8; j++) acc[i][j] = 0.f;

    size_t sbase = (size_t)b * Sc + (size_t)c * CHc;
    for (int st = 0; st < 4; st++) {
        __syncthreads();
        for (int idx = tid; idx < 64*64; idx += 256) {
            int r = idx >> 6, p = idx & 63;
            int sl = st*64 + r;
            float x = xbc[(sbase + sl)*CONVDc + h*Pc + p];
            float d = dt[(sbase + sl)*Hc + h];
            sXd[r*68 + p] = x * d * __expf(sumA - sAcum[sl]);
        }
        for (int idx = tid; idx < 64*Nc; idx += 256) {
            int r = idx >> 7, n = idx & 127;
            int sl = st*64 + r;
            sB[r*132 + n] = xbc[(sbase + sl)*CONVDc + INTERc + n];
        }
        __syncthreads();
#pragma unroll 8
        for (int k = 0; k < 64; k++) {
            float4 av = *(const float4*)&sXd[k*68 + tr*4];
            float4 b0 = *(const float4*)&sB [k*132 + tc*8];
            float4 b1 = *(const float4*)&sB [k*132 + tc*8 + 4];
            float a[4] = {av.x, av.y, av.z, av.w};
            float bb[8] = {b0.x,b0.y,b0.z,b0.w,b1.x,b1.y,b1.z,b1.w};
#pragma unroll
            for (int i = 0; i < 4; i++)
#pragma unroll
                for (int j = 0; j < 8; j++) acc[i][j] += a[i]*bb[j];
        }
    }
    size_t obase = ((((size_t)b*NCHc + c)*Hc + h)*Pc)*Nc;
#pragma unroll
    for (int i = 0; i < 4; i++) {
        int p = tr*4 + i;
        *(float4*)&states[obase + (size_t)p*Nc + tc*8]     = make_float4(acc[i][0],acc[i][1],acc[i][2],acc[i][3]);
        *(float4*)&states[obase + (size_t)p*Nc + tc*8 + 4] = make_float4(acc[i][4],acc[i][5],acc[i][6],acc[i][7]);
    }
}

// ============================================================================
// Y_diag:  Y[l,p] = sum_{s<=l} (C_l . B_s) * exp(Acum[l]-Acum[s]) * x[s,p]*dt[s]
// One block per (b,c,h). 64x64 output tiles, lower-triangular tile pairs only.
// ============================================================================
#define YD_SMEM ((128*68*2 + 64*68*2) * 4)
__global__ __launch_bounds__(256) void ydiag_kernel(
    const float* __restrict__ xbc, const float* __restrict__ dt,
    const float* __restrict__ acum, float* __restrict__ y)
{
    int h = blockIdx.x, c = blockIdx.y, b = blockIdx.z;
    extern __shared__ float sm0[];
    float* sCt = sm0;                 // [n=128][l=64]
    float* sBt = sm0 + 128*68;        // [n=128][s=64]
    float* sX  = sm0 + 128*68*2;      // [s=64][p=64]
    float* sM  = sm0 + 128*68*2 + 64*68; // [s=64][l=64]
    __shared__ float sAcum[CHc];

    int tid = threadIdx.x;
    size_t abase = ((size_t)(b*Hc + h)*NCHc + c)*CHc;
    for (int i = tid; i < CHc; i += 256) sAcum[i] = acum[abase + i];

    int tr = tid >> 4, tc = tid & 15;
    size_t sbase = (size_t)b * Sc + (size_t)c * CHc;

    for (int lt = 0; lt < 4; lt++) {
        __syncthreads();
        for (int idx = tid; idx < 64*128; idx += 256) {
            int i = idx >> 7, n = idx & 127;
            sCt[n*68 + i] = xbc[(sbase + lt*64 + i)*CONVDc + INTERc + Nc + n];
        }
        float yacc[4][4];
#pragma unroll
        for (int i = 0; i < 4; i++)
#pragma unroll
            for (int j = 0; j < 4; j++) yacc[i][j] = 0.f;

        for (int st = 0; st <= lt; st++) {
            __syncthreads();
            for (int idx = tid; idx < 64*128; idx += 256) {
                int i = idx >> 7, n = idx & 127;
                sBt[n*68 + i] = xbc[(sbase + st*64 + i)*CONVDc + INTERc + n];
            }
            for (int idx = tid; idx < 64*64; idx += 256) {
                int i = idx >> 6, p = idx & 63;
                int sl = st*64 + i;
                sX[i*68 + p] = xbc[(sbase + sl)*CONVDc + h*Pc + p] * dt[(sbase + sl)*Hc + h];
            }
            __syncthreads();
            // Mt[l, s'] = C_l . B_s'  (contract n=128)
            float macc[4][4];
#pragma unroll
            for (int i = 0; i < 4; i++)
#pragma unroll
                for (int j = 0; j < 4; j++) macc[i][j] = 0.f;
#pragma unroll 8
            for (int n = 0; n < 128; n++) {
                float4 av = *(const float4*)&sCt[n*68 + tr*4];
                float4 bv = *(const float4*)&sBt[n*68 + tc*4];
                float a[4] = {av.x,av.y,av.z,av.w};
                float bb[4] = {bv.x,bv.y,bv.z,bv.w};
#pragma unroll
                for (int i = 0; i < 4; i++)
#pragma unroll
                    for (int j = 0; j < 4; j++) macc[i][j] += a[i]*bb[j];
            }
            // apply decay mask, store transposed to sM[s'][l]
#pragma unroll
            for (int i = 0; i < 4; i++) {
                int lg = lt*64 + tr*4 + i;
#pragma unroll
                for (int j = 0; j < 4; j++) {
                    int sg = st*64 + tc*4 + j;
                    float v = (sg <= lg) ? macc[i][j] * __expf(sAcum[lg] - sAcum[sg]) : 0.f;
                    sM[(tc*4 + j)*68 + tr*4 + i] = v;
                }
            }
            __syncthreads();
            // Y[l,p] += sum_{s'} M[l,s'] * X[s',p]
#pragma unroll 8
            for (int k = 0; k < 64; k++) {
                float4 av = *(const float4*)&sM[k*68 + tr*4];
                float4 bv = *(const float4*)&sX[k*68 + tc*4];
                float a[4] = {av.x,av.y,av.z,av.w};
                float bb[4] = {bv.x,bv.y,bv.z,bv.w};
#pragma unroll
                for (int i = 0; i < 4; i++)
#pragma unroll
                    for (int j = 0; j < 4; j++) yacc[i][j] += a[i]*bb[j];
            }
        }
        // write Y_diag tile
#pragma unroll
        for (int i = 0; i < 4; i++) {
            size_t row = sbase + lt*64 + tr*4 + i;
            *(float4*)&y[row*INTERc + h*Pc + tc*4] =
                make_float4(yacc[i][0], yacc[i][1], yacc[i][2], yacc[i][3]);
        }
    }
}

// ============================================================================
// Inter-chunk scan over 8 chunks: prev_{c+1} = prev_c*exp(sumA_c) + local_c.
// In-place: states[b,c,h] becomes the state ENTERING chunk c.
// One block per (b,h), state matrix in registers (8 float4 per thread).
// ============================================================================
__global__ __launch_bounds__(256) void chunk_scan_kernel(
    const float* __restrict__ suma, float* __restrict__ states)
{
    int h = blockIdx.x, b = blockIdx.y;
    int tid = threadIdx.x;
    float4 prev[8];
#pragma unroll
    for (int k = 0; k < 8; k++) prev[k] = make_float4(0.f,0.f,0.f,0.f);
    for (int c = 0; c < NCHc; c++) {
        size_t base = ((((size_t)b*NCHc + c)*Hc + h)*Pc)*Nc;
        float dec = __expf(suma[(b*Hc + h)*NCHc + c]);
#pragma unroll
        for (int k = 0; k < 8; k++) {
            float4* ptr = (float4*)&states[base + (size_t)(k*256 + tid)*4];
            float4 loc = *ptr;
            *ptr = prev[k];
            prev[k].x = prev[k].x*dec + loc.x;
            prev[k].y = prev[k].y*dec + loc.y;
            prev[k].z = prev[k].z*dec + loc.z;
            prev[k].w = prev[k].w*dec + loc.w;
        }
    }
}

// ============================================================================
// Y_off:  Y[l,p] += exp(Acum[l]) * sum_n C[l,n]*prev[p,n]  + D[h]*x[l,p]
// One block per (b,c,h).
// ============================================================================
#define YO_SMEM ((128*68*2) * 4)
__global__ __launch_bounds__(256) void yoff_kernel(
    const float* __restrict__ xbc, const float* __restrict__ acum,
    const float* __restrict__ states, const float* __restrict__ D,
    float* __restrict__ y)
{
    int h = blockIdx.x, c = blockIdx.y, b = blockIdx.z;
    extern __shared__ float sm0[];
    float* sCt = sm0;            // [n=128][l=64], pre-scaled by exp(Acum[l])
    float* sSt = sm0 + 128*68;   // [n=128][p=64]
    __shared__ float sAcum[CHc];

    int tid = threadIdx.x;
    size_t abase = ((size_t)(b*Hc + h)*NCHc + c)*CHc;
    for (int i = tid; i < CHc; i += 256) sAcum[i] = acum[abase + i];
    __syncthreads();

    size_t stbase = ((((size_t)b*NCHc + c)*Hc + h)*Pc)*Nc;
    for (int idx = tid; idx < Pc*Nc; idx += 256) {
        int p = idx >> 7, n = idx & 127;
        sSt[n*68 + p] = states[stbase + (size_t)p*Nc + n];
    }

    int tr = tid >> 4, tc = tid & 15;
    float Dh = D[h];
    size_t sbase = (size_t)b * Sc + (size_t)c * CHc;

    for (int lt = 0; lt < 4; lt++) {
        __syncthreads();
        for (int idx = tid; idx < 64*128; idx += 256) {
            int i = idx >> 7, n = idx & 127;
            float sc = __expf(sAcum[lt*64 + i]);
            sCt[n*68 + i] = xbc[(sbase + lt*64 + i)*CONVDc + INTERc + Nc + n] * sc;
        }
        __syncthreads();
        float acc[4][4];
#pragma unroll
        for (int i = 0; i < 4; i++)
#pragma unroll
            for (int j = 0; j < 4; j++) acc[i][j] = 0.f;
#pragma unroll 8
        for (int n = 0; n < 128; n++) {
            float4 av = *(const float4*)&sCt[n*68 + tr*4];
            float4 bv = *(const float4*)&sSt[n*68 + tc*4];
            float a[4] = {av.x,av.y,av.z,av.w};
            float bb[4] = {bv.x,bv.y,bv.z,bv.w};
#pragma unroll
            for (int i = 0; i < 4; i++)
#pragma unroll
                for (int j = 0; j < 4; j++) acc[i][j] += a[i]*bb[j];
        }
#pragma unroll
        for (int i = 0; i < 4; i++) {
            size_t row = sbase + lt*64 + tr*4 + i;
            float4 yv = *(float4*)&y[row*INTERc + h*Pc + tc*4];
            float4 xv = *(const float4*)&xbc[row*CONVDc + h*Pc + tc*4];
            yv.x += acc[i][0] + Dh*xv.x;
            yv.y += acc[i][1] + Dh*xv.y;
            yv.z += acc[i][2] + Dh*xv.z;
            yv.w += acc[i][3] + Dh*xv.w;
            *(float4*)&y[row*INTERc + h*Pc + tc*4] = yv;
        }
    }
}

// ============================================================================
// yg = y * silu(gate); RMSNorm over INTER with norm_w. In-place on y.
// One block per (b,s) row.
// ============================================================================
__global__ __launch_bounds__(256) void gatenorm_kernel(
    const float* __restrict__ proj, const float* __restrict__ norm_w,
    float* __restrict__ y)
{
    int row = blockIdx.x;
    const float* g = proj + (size_t)row * PROJc;   // gate = first INTER cols
    float* yr = y + (size_t)row * INTERc;
    int tid = threadIdx.x;

    float4 yv[4];
    float ss = 0.f;
#pragma unroll
    for (int k = 0; k < 4; k++) {
        int e = (k*256 + tid) * 4;
        float4 yy = *(const float4*)&yr[e];
        float4 gg = *(const float4*)&g[e];
        gg.x = gg.x / (1.f + expf(-gg.x));
        gg.y = gg.y / (1.f + expf(-gg.y));
        gg.z = gg.z / (1.f + expf(-gg.z));
        gg.w = gg.w / (1.f + expf(-gg.w));
        yy.x *= gg.x; yy.y *= gg.y; yy.z *= gg.z; yy.w *= gg.w;
        ss += yy.x*yy.x + yy.y*yy.y + yy.z*yy.z + yy.w*yy.w;
        yv[k] = yy;
    }
#pragma unroll
    for (int off = 16; off > 0; off >>= 1)
        ss += __shfl_xor_sync(0xFFFFFFFFu, ss, off);
    __shared__ float red[8];
    __shared__ float s_scale;
    if ((tid & 31) == 0) red[tid >> 5] = ss;
    __syncthreads();
    if (tid == 0) {
        float t = 0.f;
#pragma unroll
        for (int i = 0; i < 8; i++) t += red[i];
        s_scale = rsqrtf(t / (float)INTERc + EPSc);
    }
    __syncthreads();
    float sc = s_scale;
#pragma unroll
    for (int k = 0; k < 4; k++) {
        int e = (k*256 + tid) * 4;
        float4 wv = *(const float4*)&norm_w[e];
        float4 o;
        o.x = yv[k].x * sc * wv.x;
        o.y = yv[k].y * sc * wv.y;
        o.z = yv[k].z * sc * wv.z;
        o.w = yv[k].w * sc * wv.w;
        *(float4*)&yr[e] = o;
    }
}

// ============================================================================
extern "C" void kernel_launch(void* const* d_in, const int* in_sizes, int n_in,
                              void* d_out, int out_size)
{
    const float* x       = (const float*)d_in[0];
    // d_in[1] = mask (all ones, unused by reference math)
    const float* w_in    = (const float*)d_in[2];
    const float* conv_w  = (const float*)d_in[3];
    const float* conv_b  = (const float*)d_in[4];
    const float* A_log   = (const float*)d_in[5];
    const float* dt_bias = (const float*)d_in[6];
    const float* Dv      = (const float*)d_in[7];
    const float* norm_w  = (const float*)d_in[8];
    const float* w_out   = (const float*)d_in[9];
    float* out = (float*)d_out;

    void *p;
    cudaGetSymbolAddress(&p, g_proj);   float* proj   = (float*)p;
    cudaGetSymbolAddress(&p, g_xbc);    float* xbc    = (float*)p;
    cudaGetSymbolAddress(&p, g_dt);     float* dtb    = (float*)p;
    cudaGetSymbolAddress(&p, g_acum);   float* acum   = (float*)p;
    cudaGetSymbolAddress(&p, g_suma);   float* suma   = (float*)p;
    cudaGetSymbolAddress(&p, g_states); float* states = (float*)p;
    cudaGetSymbolAddress(&p, g_y);      float* yb     = (float*)p;

    cudaFuncSetAttribute(local_state_kernel, cudaFuncAttributeMaxDynamicSharedMemorySize, LS_SMEM);
    cudaFuncSetAttribute(ydiag_kernel,       cudaFuncAttributeMaxDynamicSharedMemorySize, YD_SMEM);
    cudaFuncSetAttribute(yoff_kernel,        cudaFuncAttributeMaxDynamicSharedMemorySize, YO_SMEM);

    // 1) in_proj GEMM: [4096,2048] x [8512,2048]^T
    {
        dim3 grid((PROJc + 127) / 128, ROWSc / 128);
        sgemm_nt<<<grid, 256>>>(x, w_in, proj, ROWSc, PROJc, Ec);
    }
    // 2) depthwise conv + SiLU
    {
        dim3 grid(CONVDc / 256, Bc);
        conv_silu_kernel<<<grid, 256>>>(proj, conv_w, conv_b, xbc);
    }
    // 3) dt softplus + per-chunk cumsum of A*dt
    {
        dim3 grid(Hc, NCHc, Bc);
        dt_scan_kernel<<<grid, 256>>>(proj, A_log, dt_bias, dtb, acum, suma);
    }
    // 4) local chunk states
    {
        dim3 grid(Hc, NCHc, Bc);
        local_state_kernel<<<grid, 256, LS_SMEM>>>(xbc, dtb, acum, states);
    }
    // 5) Y_diag
    {
        dim3 grid(Hc, NCHc, Bc);
        ydiag_kernel<<<grid, 256, YD_SMEM>>>(xbc, dtb, acum, yb);
    }
    // 6) inter-chunk scan
    {
        dim3 grid(Hc, Bc);
        chunk_scan_kernel<<<grid, 256>>>(suma, states);
    }
    // 7) Y_off + D residual
    {
        dim3 grid(Hc, NCHc, Bc);
        yoff_kernel<<<grid, 256, YO_SMEM>>>(xbc, acum, states, Dv, yb);
    }
    // 8) gate + RMSNorm
    {
        gatenorm_kernel<<<ROWSc, 256>>>(proj, norm_w, yb);
    }
    // 9) out_proj GEMM: [4096,4096] x [2048,4096]^T -> d_out
    {
        dim3 grid(Ec / 128, ROWSc / 128);
        sgemm_nt<<<grid, 256>>>(yb, w_out, out, ROWSc, Ec, INTERc);
    }
}

// round 3
// speedup vs baseline: 1.7584x; 1.7584x over previous
#include <cuda_runtime.h>
#include <cuda_bf16.h>
#include <math.h>
#include <stdint.h>

// ---------------- problem constants ----------------
#define Bc   2
#define Sc   2048
#define Ec   2048
#define Hc   64
#define Pc   64
#define Nc   128
#define Kc   4
#define CHc  256
#define NCHc 8
#define INTERc 4096
#define CONVDc 4352
#define PROJc  8512
#define ROWSc  4096          // B*S
#define EPSc   1e-5f

// ---------------- scratch (static device globals; no allocation) -------------
__device__ float g_proj[(size_t)ROWSc * PROJc];
__device__ float g_xbc [(size_t)ROWSc * CONVDc];
__device__ float g_dt  [ROWSc * Hc];
__device__ float g_acum[Bc * Hc * NCHc * CHc];
__device__ float g_suma[Bc * Hc * NCHc];
__device__ float g_states[(size_t)Bc * NCHc * Hc * Pc * Nc];
__device__ float g_y   [(size_t)ROWSc * INTERc];

__device__ __nv_bfloat16 g_xhi[(size_t)ROWSc * Ec];
__device__ __nv_bfloat16 g_xlo[(size_t)ROWSc * Ec];
__device__ __nv_bfloat16 g_whi[(size_t)PROJc * Ec];
__device__ __nv_bfloat16 g_wlo[(size_t)PROJc * Ec];
__device__ __nv_bfloat16 g_yhi[(size_t)ROWSc * INTERc];
__device__ __nv_bfloat16 g_ylo[(size_t)ROWSc * INTERc];
__device__ __nv_bfloat16 g_wohi[(size_t)Ec * INTERc];
__device__ __nv_bfloat16 g_wolo[(size_t)Ec * INTERc];

// ================= helpers (sm_100 base target: mma.sync / ldmatrix / cp.async)
__device__ __forceinline__ uint32_t smem_u32(const void* p) {
    uint32_t a;
    asm("{ .reg .u64 t; cvta.to.shared.u64 t, %1; cvt.u32.u64 %0, t; }"
        : "=r"(a) : "l"(p));
    return a;
}
__device__ __forceinline__ void cp16(uint32_t d, const void* g, int sz) {
    asm volatile("cp.async.ca.shared.global [%0], [%1], 16, %2;"
                 :: "r"(d), "l"(g), "r"(sz));
}
__device__ __forceinline__ void ldmx4(uint32_t* r, uint32_t addr) {
    asm volatile("ldmatrix.sync.aligned.m8n8.x4.shared.b16 {%0,%1,%2,%3}, [%4];"
                 : "=r"(r[0]), "=r"(r[1]), "=r"(r[2]), "=r"(r[3]) : "r"(addr));
}
__device__ __forceinline__ void ldmx2(uint32_t* r, uint32_t addr) {
    asm volatile("ldmatrix.sync.aligned.m8n8.x2.shared.b16 {%0,%1}, [%2];"
                 : "=r"(r[0]), "=r"(r[1]) : "r"(addr));
}
__device__ __forceinline__ void mma16816(float* d, const uint32_t* a, const uint32_t* b) {
    asm volatile(
        "mma.sync.aligned.m16n8k16.row.col.f32.bf16.bf16.f32 "
        "{%0,%1,%2,%3}, {%4,%5,%6,%7}, {%8,%9}, {%0,%1,%2,%3};"
        : "+f"(d[0]), "+f"(d[1]), "+f"(d[2]), "+f"(d[3])
        : "r"(a[0]), "r"(a[1]), "r"(a[2]), "r"(a[3]), "r"(b[0]), "r"(b[1]));
}

// ============================================================================
// Split fp32 -> bf16 hi + bf16 lo
// ============================================================================
__global__ __launch_bounds__(256) void split_bf16_kernel(
    const float* __restrict__ src, __nv_bfloat16* __restrict__ hi,
    __nv_bfloat16* __restrict__ lo, int n4)
{
    int i = blockIdx.x * 256 + threadIdx.x;
    if (i >= n4) return;
    float4 v = ((const float4*)src)[i];
    float f[4] = {v.x, v.y, v.z, v.w};
    uint32_t hh[2], ll[2];
#pragma unroll
    for (int p = 0; p < 2; p++) {
        __nv_bfloat16 h0 = __float2bfloat16(f[p*2+0]);
        __nv_bfloat16 h1 = __float2bfloat16(f[p*2+1]);
        __nv_bfloat16 l0 = __float2bfloat16(f[p*2+0] - __bfloat162float(h0));
        __nv_bfloat16 l1 = __float2bfloat16(f[p*2+1] - __bfloat162float(h1));
        hh[p] = (uint32_t)__bfloat16_as_ushort(h0) | ((uint32_t)__bfloat16_as_ushort(h1) << 16);
        ll[p] = (uint32_t)__bfloat16_as_ushort(l0) | ((uint32_t)__bfloat16_as_ushort(l1) << 16);
    }
    ((uint2*)hi)[i] = make_uint2(hh[0], hh[1]);
    ((uint2*)lo)[i] = make_uint2(ll[0], ll[1]);
}

// ============================================================================
// bf16 split GEMM via mma.sync:  C[M,Nt] = (Ahi+Alo)(Bhi+Blo)^T (3-term)
// 128x128 tile, BK=32, 3-stage cp.async pipeline, 8 warps, 64x32 per warp.
// SMEM rows padded to 80B (conflict-free ldmatrix without swizzle).
// ============================================================================
#define ROWB 80
#define BUFB (128 * ROWB)         // 10240
#define STAGEB (4 * BUFB)         // 40960
#define GEMM_SMEM (3 * STAGEB)    // 122880

__global__ __launch_bounds__(256, 1) void gemm_mma(
    const __nv_bfloat16* __restrict__ Ahi, const __nv_bfloat16* __restrict__ Alo,
    const __nv_bfloat16* __restrict__ Bhi, const __nv_bfloat16* __restrict__ Blo,
    float* __restrict__ C, int M, int Nt, int K)
{
    extern __shared__ char sm[];
    const uint32_t sbase = smem_u32(sm);
    const int tid = threadIdx.x, lane = tid & 31, wid = tid >> 5;
    const int bm = blockIdx.y * 128, bn = blockIdx.x * 128;
    const int wm = (wid & 1) * 64, wn = (wid >> 1) * 32;

    float acc[4][4][4];
#pragma unroll
    for (int i = 0; i < 4; i++)
#pragma unroll
        for (int j = 0; j < 4; j++)
#pragma unroll
            for (int k = 0; k < 4; k++) acc[i][j][k] = 0.f;

    const int nch = K >> 5;

    // ---- stage loader: 4 bufs x 128 rows x 64B, one cp.async 16B per slot
    auto issue_stage = [&](int ci, int s) {
        const int k0 = ci << 5;
        const uint32_t stb = sbase + s * STAGEB;
        const int ck = tid & 3;
#pragma unroll
        for (int t = 0; t < 8; t++) {
            const int buf = t >> 1;                      // 0:Ahi 1:Alo 2:Bhi 3:Blo
            const int row = (t & 1) * 64 + (tid >> 2);
            const __nv_bfloat16* src = (buf == 0) ? Ahi : (buf == 1) ? Alo
                                      : (buf == 2) ? Bhi : Blo;
            const int rb = (buf < 2) ? bm : bn;
            const bool valid = (buf < 2) || (bn + row < Nt);
            const int grow = valid ? (rb + row) : 0;
            const char* g = (const char*)(src + (size_t)grow * K + k0) + ck * 16;
            cp16(stb + buf * BUFB + row * ROWB + ck * 16, g, valid ? 16 : 0);
        }
        asm volatile("cp.async.commit_group;" ::: "memory");
    };

    auto compute_stage = [&](int s) {
        const uint32_t stb = sbase + s * STAGEB;
        const uint32_t aHiB = stb, aLoB = stb + BUFB;
        const uint32_t bHiB = stb + 2 * BUFB, bLoB = stb + 3 * BUFB;
#pragma unroll
        for (int ks = 0; ks < 2; ks++) {
            const uint32_t aoff = (uint32_t)(wm + (lane & 15)) * ROWB
                                + (uint32_t)(ks * 2 + (lane >> 4)) * 16;
            const uint32_t boff = (uint32_t)(wn + (lane & 7)) * ROWB
                                + (uint32_t)(ks * 2 + ((lane >> 3) & 1)) * 16;
            uint32_t ahi[4][4], alo[4][4], bhi[4][2], blo[4][2];
#pragma unroll
            for (int mt = 0; mt < 4; mt++) ldmx4(ahi[mt], aHiB + aoff + mt * 16 * ROWB);
#pragma unroll
            for (int nt = 0; nt < 4; nt++) ldmx2(bhi[nt], bHiB + boff + nt * 8 * ROWB);
#pragma unroll
            for (int mt = 0; mt < 4; mt++)
#pragma unroll
                for (int nt = 0; nt < 4; nt++) mma16816(acc[mt][nt], ahi[mt], bhi[nt]);
#pragma unroll
            for (int mt = 0; mt < 4; mt++) ldmx4(alo[mt], aLoB + aoff + mt * 16 * ROWB);
#pragma unroll
            for (int mt = 0; mt < 4; mt++)
#pragma unroll
                for (int nt = 0; nt < 4; nt++) mma16816(acc[mt][nt], alo[mt], bhi[nt]);
#pragma unroll
            for (int nt = 0; nt < 4; nt++) ldmx2(blo[nt], bLoB + boff + nt * 8 * ROWB);
#pragma unroll
            for (int mt = 0; mt < 4; mt++)
#pragma unroll
                for (int nt = 0; nt < 4; nt++) mma16816(acc[mt][nt], ahi[mt], blo[nt]);
        }
    };

    issue_stage(0, 0);
    issue_stage(1, 1);
    for (int ci = 0; ci < nch; ci++) {
        asm volatile("cp.async.wait_group 1;" ::: "memory");
        __syncthreads();
        if (ci + 2 < nch) issue_stage(ci + 2, (ci + 2) % 3);
        else asm volatile("cp.async.commit_group;" ::: "memory");
        compute_stage(ci % 3);
    }

    // epilogue
#pragma unroll
    for (int mt = 0; mt < 4; mt++) {
        const int r0 = bm + wm + mt * 16 + (lane >> 2);
#pragma unroll
        for (int nt = 0; nt < 4; nt++) {
            const int c0 = bn + wn + nt * 8 + (lane & 3) * 2;
            if (c0 < Nt) {
                *(float2*)&C[(size_t)r0 * Nt + c0] =
                    make_float2(acc[mt][nt][0], acc[mt][nt][1]);
                *(float2*)&C[(size_t)(r0 + 8) * Nt + c0] =
                    make_float2(acc[mt][nt][2], acc[mt][nt][3]);
            }
        }
    }
}

// ============================================================================
// Depthwise causal conv (K=4) + bias + SiLU
// ============================================================================
__global__ __launch_bounds__(256) void conv_silu_kernel(
    const float* __restrict__ proj, const float* __restrict__ conv_w,
    const float* __restrict__ conv_b, float* __restrict__ xbc)
{
    int c = blockIdx.x * blockDim.x + threadIdx.x;
    int b = blockIdx.y;
    if (c >= CONVDc) return;
    float w0 = conv_w[c*Kc+0], w1 = conv_w[c*Kc+1];
    float w2 = conv_w[c*Kc+2], w3 = conv_w[c*Kc+3];
    float bias = conv_b[c];
    const float* src = proj + (size_t)b * Sc * PROJc + INTERc + c;
    float* dst = xbc + (size_t)b * Sc * CONVDc + c;
    float x0 = 0.f, x1 = 0.f, x2 = 0.f;
    for (int s = 0; s < Sc; s++) {
        float x3 = src[(size_t)s * PROJc];
        float v  = w0*x0 + w1*x1 + w2*x2 + w3*x3 + bias;
        v = v / (1.f + expf(-v));
        dst[(size_t)s * CONVDc] = v;
        x0 = x1; x1 = x2; x2 = x3;
    }
}

// ============================================================================
// dt softplus + per-chunk cumsum of A*dt
// ============================================================================
__global__ __launch_bounds__(256) void dt_scan_kernel(
    const float* __restrict__ proj, const float* __restrict__ A_log,
    const float* __restrict__ dt_bias, float* __restrict__ dt_out,
    float* __restrict__ acum, float* __restrict__ suma)
{
    int h = blockIdx.x, c = blockIdx.y, b = blockIdx.z;
    int l = threadIdx.x;
    int s = c * CHc + l;
    float raw = proj[(size_t)(b*Sc + s)*PROJc + INTERc + CONVDc + h] + dt_bias[h];
    float sp  = (raw > 20.f) ? raw : log1pf(expf(raw));
    dt_out[(size_t)(b*Sc + s)*Hc + h] = sp;
    float a = -expf(A_log[h]) * sp;

    __shared__ float sb[CHc];
    sb[l] = a;
    __syncthreads();
    for (int off = 1; off < CHc; off <<= 1) {
        float t = (l >= off) ? sb[l - off] : 0.f;
        __syncthreads();
        sb[l] += t;
        __syncthreads();
    }
    acum[((size_t)(b*Hc + h)*NCHc + c)*CHc + l] = sb[l];
    if (l == CHc - 1) suma[(b*Hc + h)*NCHc + c] = sb[l];
}

// ============================================================================
// Local chunk state
// ============================================================================
#define LS_SMEM ((64*68 + 64*132) * 4)
__global__ __launch_bounds__(256) void local_state_kernel(
    const float* __restrict__ xbc, const float* __restrict__ dt,
    const float* __restrict__ acum, float* __restrict__ states)
{
    int h = blockIdx.x, c = blockIdx.y, b = blockIdx.z;
    extern __shared__ float sm0[];
    float* sXd = sm0;
    float* sB  = sm0 + 64*68;
    __shared__ float sAcum[CHc];

    int tid = threadIdx.x;
    size_t abase = ((size_t)(b*Hc + h)*NCHc + c)*CHc;
    for (int i = tid; i < CHc; i += 256) sAcum[i] = acum[abase + i];
    __syncthreads();
    float sumA = sAcum[CHc - 1];

    int tr = tid >> 4, tc = tid & 15;
    float acc[4][8];
#pragma unroll
    for (int i = 0; i < 4; i++)
#pragma unroll
        for (int j = 0; j < 8; j++) acc[i][j] = 0.f;

    size_t sbase = (size_t)b * Sc + (size_t)c * CHc;
    for (int st = 0; st < 4; st++) {
        __syncthreads();
        for (int idx = tid; idx < 64*64; idx += 256) {
            int r = idx >> 6, p = idx & 63;
            int sl = st*64 + r;
            float x = xbc[(sbase + sl)*CONVDc + h*Pc + p];
            float d = dt[(sbase + sl)*Hc + h];
            sXd[r*68 + p] = x * d * __expf(sumA - sAcum[sl]);
        }
        for (int idx = tid; idx < 64*Nc; idx += 256) {
            int r = idx >> 7, n = idx & 127;
            int sl = st*64 + r;
            sB[r*132 + n] = xbc[(sbase + sl)*CONVDc + INTERc + n];
        }
        __syncthreads();
#pragma unroll 8
        for (int k = 0; k < 64; k++) {
            float4 av = *(const float4*)&sXd[k*68 + tr*4];
            float4 b0 = *(const float4*)&sB [k*132 + tc*8];
            float4 b1 = *(const float4*)&sB [k*132 + tc*8 + 4];
            float a[4] = {av.x, av.y, av.z, av.w};
            float bb[8] = {b0.x,b0.y,b0.z,b0.w,b1.x,b1.y,b1.z,b1.w};
#pragma unroll
            for (int i = 0; i < 4; i++)
#pragma unroll
                for (int j = 0; j < 8; j++) acc[i][j] += a[i]*bb[j];
        }
    }
    size_t obase = ((((size_t)b*NCHc + c)*Hc + h)*Pc)*Nc;
#pragma unroll
    for (int i = 0; i < 4; i++) {
        int p = tr*4 + i;
        *(float4*)&states[obase + (size_t)p*Nc + tc*8]     = make_float4(acc[i][0],acc[i][1],acc[i][2],acc[i][3]);
        *(float4*)&states[obase + (size_t)p*Nc + tc*8 + 4] = make_float4(acc[i][4],acc[i][5],acc[i][6],acc[i][7]);
    }
}

// ============================================================================
// Y_diag
// ============================================================================
#define YD_SMEM ((128*68*2 + 64*68*2) * 4)
__global__ __launch_bounds__(256) void ydiag_kernel(
    const float* __restrict__ xbc, const float* __restrict__ dt,
    const float* __restrict__ acum, float* __restrict__ y)
{
    int h = blockIdx.x, c = blockIdx.y, b = blockIdx.z;
    extern __shared__ float sm0[];
    float* sCt = sm0;
    float* sBt = sm0 + 128*68;
    float* sX  = sm0 + 128*68*2;
    float* sM  = sm0 + 128*68*2 + 64*68;
    __shared__ float sAcum[CHc];

    int tid = threadIdx.x;
    size_t abase = ((size_t)(b*Hc + h)*NCHc + c)*CHc;
    for (int i = tid; i < CHc; i += 256) sAcum[i] = acum[abase + i];

    int tr = tid >> 4, tc = tid & 15;
    size_t sbase = (size_t)b * Sc + (size_t)c * CHc;

    for (int lt = 0; lt < 4; lt++) {
        __syncthreads();
        for (int idx = tid; idx < 64*128; idx += 256) {
            int i = idx >> 7, n = idx & 127;
            sCt[n*68 + i] = xbc[(sbase + lt*64 + i)*CONVDc + INTERc + Nc + n];
        }
        float yacc[4][4];
#pragma unroll
        for (int i = 0; i < 4; i++)
#pragma unroll
            for (int j = 0; j < 4; j++) yacc[i][j] = 0.f;

        for (int st = 0; st <= lt; st++) {
            __syncthreads();
            for (int idx = tid; idx < 64*128; idx += 256) {
                int i = idx >> 7, n = idx & 127;
                sBt[n*68 + i] = xbc[(sbase + st*64 + i)*CONVDc + INTERc + n];
            }
            for (int idx = tid; idx < 64*64; idx += 256) {
                int i = idx >> 6, p = idx & 63;
                int sl = st*64 + i;
                sX[i*68 + p] = xbc[(sbase + sl)*CONVDc + h*Pc + p] * dt[(sbase + sl)*Hc + h];
            }
            __syncthreads();
            float macc[4][4];
#pragma unroll
            for (int i = 0; i < 4; i++)
#pragma unroll
                for (int j = 0; j < 4; j++) macc[i][j] = 0.f;
#pragma unroll 8
            for (int n = 0; n < 128; n++) {
                float4 av = *(const float4*)&sCt[n*68 + tr*4];
                float4 bv = *(const float4*)&sBt[n*68 + tc*4];
                float a[4] = {av.x,av.y,av.z,av.w};
                float bb[4] = {bv.x,bv.y,bv.z,bv.w};
#pragma unroll
                for (int i = 0; i < 4; i++)
#pragma unroll
                    for (int j = 0; j < 4; j++) macc[i][j] += a[i]*bb[j];
            }
#pragma unroll
            for (int i = 0; i < 4; i++) {
                int lg = lt*64 + tr*4 + i;
#pragma unroll
                for (int j = 0; j < 4; j++) {
                    int sg = st*64 + tc*4 + j;
                    float v = (sg <= lg) ? macc[i][j] * __expf(sAcum[lg] - sAcum[sg]) : 0.f;
                    sM[(tc*4 + j)*68 + tr*4 + i] = v;
                }
            }
            __syncthreads();
#pragma unroll 8
            for (int k = 0; k < 64; k++) {
                float4 av = *(const float4*)&sM[k*68 + tr*4];
                float4 bv = *(const float4*)&sX[k*68 + tc*4];
                float a[4] = {av.x,av.y,av.z,av.w};
                float bb[4] = {bv.x,bv.y,bv.z,bv.w};
#pragma unroll
                for (int i = 0; i < 4; i++)
#pragma unroll
                    for (int j = 0; j < 4; j++) yacc[i][j] += a[i]*bb[j];
            }
        }
#pragma unroll
        for (int i = 0; i < 4; i++) {
            size_t row = sbase + lt*64 + tr*4 + i;
            *(float4*)&y[row*INTERc + h*Pc + tc*4] =
                make_float4(yacc[i][0], yacc[i][1], yacc[i][2], yacc[i][3]);
        }
    }
}

// ============================================================================
// Inter-chunk scan
// ============================================================================
__global__ __launch_bounds__(256) void chunk_scan_kernel(
    const float* __restrict__ suma, float* __restrict__ states)
{
    int h = blockIdx.x, b = blockIdx.y;
    int tid = threadIdx.x;
    float4 prev[8];
#pragma unroll
    for (int k = 0; k < 8; k++) prev[k] = make_float4(0.f,0.f,0.f,0.f);
    for (int c = 0; c < NCHc; c++) {
        size_t base = ((((size_t)b*NCHc + c)*Hc + h)*Pc)*Nc;
        float dec = __expf(suma[(b*Hc + h)*NCHc + c]);
#pragma unroll
        for (int k = 0; k < 8; k++) {
            float4* ptr = (float4*)&states[base + (size_t)(k*256 + tid)*4];
            float4 loc = *ptr;
            *ptr = prev[k];
            prev[k].x = prev[k].x*dec + loc.x;
            prev[k].y = prev[k].y*dec + loc.y;
            prev[k].z = prev[k].z*dec + loc.z;
            prev[k].w = prev[k].w*dec + loc.w;
        }
    }
}

// ============================================================================
// Y_off + D residual
// ============================================================================
#define YO_SMEM ((128*68*2) * 4)
__global__ __launch_bounds__(256) void yoff_kernel(
    const float* __restrict__ xbc, const float* __restrict__ acum,
    const float* __restrict__ states, const float* __restrict__ D,
    float* __restrict__ y)
{
    int h = blockIdx.x, c = blockIdx.y, b = blockIdx.z;
    extern __shared__ float sm0[];
    float* sCt = sm0;
    float* sSt = sm0 + 128*68;
    __shared__ float sAcum[CHc];

    int tid = threadIdx.x;
    size_t abase = ((size_t)(b*Hc + h)*NCHc + c)*CHc;
    for (int i = tid; i < CHc; i += 256) sAcum[i] = acum[abase + i];
    __syncthreads();

    size_t stbase = ((((size_t)b*NCHc + c)*Hc + h)*Pc)*Nc;
    for (int idx = tid; idx < Pc*Nc; idx += 256) {
        int p = idx >> 7, n = idx & 127;
        sSt[n*68 + p] = states[stbase + (size_t)p*Nc + n];
    }

    int tr = tid >> 4, tc = tid & 15;
    float Dh = D[h];
    size_t sbase = (size_t)b * Sc + (size_t)c * CHc;

    for (int lt = 0; lt < 4; lt++) {
        __syncthreads();
        for (int idx = tid; idx < 64*128; idx += 256) {
            int i = idx >> 7, n = idx & 127;
            float sc = __expf(sAcum[lt*64 + i]);
            sCt[n*68 + i] = xbc[(sbase + lt*64 + i)*CONVDc + INTERc + Nc + n] * sc;
        }
        __syncthreads();
        float acc[4][4];
#pragma unroll
        for (int i = 0; i < 4; i++)
#pragma unroll
            for (int j = 0; j < 4; j++) acc[i][j] = 0.f;
#pragma unroll 8
        for (int n = 0; n < 128; n++) {
            float4 av = *(const float4*)&sCt[n*68 + tr*4];
            float4 bv = *(const float4*)&sSt[n*68 + tc*4];
            float a[4] = {av.x,av.y,av.z,av.w};
            float bb[4] = {bv.x,bv.y,bv.z,bv.w};
#pragma unroll
            for (int i = 0; i < 4; i++)
#pragma unroll
                for (int j = 0; j < 4; j++) acc[i][j] += a[i]*bb[j];
        }
#pragma unroll
        for (int i = 0; i < 4; i++) {
            size_t row = sbase + lt*64 + tr*4 + i;
            float4 yv = *(float4*)&y[row*INTERc + h*Pc + tc*4];
            float4 xv = *(const float4*)&xbc[row*CONVDc + h*Pc + tc*4];
            yv.x += acc[i][0] + Dh*xv.x;
            yv.y += acc[i][1] + Dh*xv.y;
            yv.z += acc[i][2] + Dh*xv.z;
            yv.w += acc[i][3] + Dh*xv.w;
            *(float4*)&y[row*INTERc + h*Pc + tc*4] = yv;
        }
    }
}

// ============================================================================
// yg = y * silu(gate); RMSNorm; emit bf16 hi/lo split for out_proj GEMM.
// ============================================================================
__global__ __launch_bounds__(256) void gatenorm_kernel(
    const float* __restrict__ proj, const float* __restrict__ norm_w,
    const float* __restrict__ y,
    __nv_bfloat16* __restrict__ yhi, __nv_bfloat16* __restrict__ ylo)
{
    int row = blockIdx.x;
    const float* g = proj + (size_t)row * PROJc;
    const float* yr = y + (size_t)row * INTERc;
    int tid = threadIdx.x;

    float4 yv[4];
    float ss = 0.f;
#pragma unroll
    for (int k = 0; k < 4; k++) {
        int e = (k*256 + tid) * 4;
        float4 yy = *(const float4*)&yr[e];
        float4 gg = *(const float4*)&g[e];
        gg.x = gg.x / (1.f + expf(-gg.x));
        gg.y = gg.y / (1.f + expf(-gg.y));
        gg.z = gg.z / (1.f + expf(-gg.z));
        gg.w = gg.w / (1.f + expf(-gg.w));
        yy.x *= gg.x; yy.y *= gg.y; yy.z *= gg.z; yy.w *= gg.w;
        ss += yy.x*yy.x + yy.y*yy.y + yy.z*yy.z + yy.w*yy.w;
        yv[k] = yy;
    }
#pragma unroll
    for (int off = 16; off > 0; off >>= 1)
        ss += __shfl_xor_sync(0xFFFFFFFFu, ss, off);
    __shared__ float red[8];
    __shared__ float s_scale;
    if ((tid & 31) == 0) red[tid >> 5] = ss;
    __syncthreads();
    if (tid == 0) {
        float t = 0.f;
#pragma unroll
        for (int i = 0; i < 8; i++) t += red[i];
        s_scale = rsqrtf(t / (float)INTERc + EPSc);
    }
    __syncthreads();
    float sc = s_scale;
#pragma unroll
    for (int k = 0; k < 4; k++) {
        int e = (k*256 + tid) * 4;
        float4 wv = *(const float4*)&norm_w[e];
        float o[4];
        o[0] = yv[k].x * sc * wv.x;
        o[1] = yv[k].y * sc * wv.y;
        o[2] = yv[k].z * sc * wv.z;
        o[3] = yv[k].w * sc * wv.w;
        uint32_t hh[2], ll[2];
#pragma unroll
        for (int p = 0; p < 2; p++) {
            __nv_bfloat16 h0 = __float2bfloat16(o[p*2+0]);
            __nv_bfloat16 h1 = __float2bfloat16(o[p*2+1]);
            __nv_bfloat16 l0 = __float2bfloat16(o[p*2+0] - __bfloat162float(h0));
            __nv_bfloat16 l1 = __float2bfloat16(o[p*2+1] - __bfloat162float(h1));
            hh[p] = (uint32_t)__bfloat16_as_ushort(h0) | ((uint32_t)__bfloat16_as_ushort(h1) << 16);
            ll[p] = (uint32_t)__bfloat16_as_ushort(l0) | ((uint32_t)__bfloat16_as_ushort(l1) << 16);
        }
        size_t eo = (size_t)row * INTERc + e;
        *(uint2*)&yhi[eo] = make_uint2(hh[0], hh[1]);
        *(uint2*)&ylo[eo] = make_uint2(ll[0], ll[1]);
    }
}

// ============================================================================
extern "C" void kernel_launch(void* const* d_in, const int* in_sizes, int n_in,
                              void* d_out, int out_size)
{
    const float* x       = (const float*)d_in[0];
    const float* w_in    = (const float*)d_in[2];
    const float* conv_w  = (const float*)d_in[3];
    const float* conv_b  = (const float*)d_in[4];
    const float* A_log   = (const float*)d_in[5];
    const float* dt_bias = (const float*)d_in[6];
    const float* Dv      = (const float*)d_in[7];
    const float* norm_w  = (const float*)d_in[8];
    const float* w_out   = (const float*)d_in[9];
    float* out = (float*)d_out;

    void *p;
    cudaGetSymbolAddress(&p, g_proj);   float* proj   = (float*)p;
    cudaGetSymbolAddress(&p, g_xbc);    float* xbc    = (float*)p;
    cudaGetSymbolAddress(&p, g_dt);     float* dtb    = (float*)p;
    cudaGetSymbolAddress(&p, g_acum);   float* acum   = (float*)p;
    cudaGetSymbolAddress(&p, g_suma);   float* suma   = (float*)p;
    cudaGetSymbolAddress(&p, g_states); float* states = (float*)p;
    cudaGetSymbolAddress(&p, g_y);      float* yb     = (float*)p;
    cudaGetSymbolAddress(&p, g_xhi);    __nv_bfloat16* xhi = (__nv_bfloat16*)p;
    cudaGetSymbolAddress(&p, g_xlo);    __nv_bfloat16* xlo = (__nv_bfloat16*)p;
    cudaGetSymbolAddress(&p, g_whi);    __nv_bfloat16* whi = (__nv_bfloat16*)p;
    cudaGetSymbolAddress(&p, g_wlo);    __nv_bfloat16* wlo = (__nv_bfloat16*)p;
    cudaGetSymbolAddress(&p, g_yhi);    __nv_bfloat16* yhi = (__nv_bfloat16*)p;
    cudaGetSymbolAddress(&p, g_ylo);    __nv_bfloat16* ylo = (__nv_bfloat16*)p;
    cudaGetSymbolAddress(&p, g_wohi);   __nv_bfloat16* wohi = (__nv_bfloat16*)p;
    cudaGetSymbolAddress(&p, g_wolo);   __nv_bfloat16* wolo = (__nv_bfloat16*)p;

    cudaFuncSetAttribute(gemm_mma,           cudaFuncAttributeMaxDynamicSharedMemorySize, GEMM_SMEM);
    cudaFuncSetAttribute(local_state_kernel, cudaFuncAttributeMaxDynamicSharedMemorySize, LS_SMEM);
    cudaFuncSetAttribute(ydiag_kernel,       cudaFuncAttributeMaxDynamicSharedMemorySize, YD_SMEM);
    cudaFuncSetAttribute(yoff_kernel,        cudaFuncAttributeMaxDynamicSharedMemorySize, YO_SMEM);

    // 0) split operands to bf16 hi/lo
    {
        int n4;
        n4 = (ROWSc * Ec) / 4;
        split_bf16_kernel<<<(n4 + 255)/256, 256>>>(x, xhi, xlo, n4);
        n4 = (PROJc * Ec) / 4;
        split_bf16_kernel<<<(n4 + 255)/256, 256>>>(w_in, whi, wlo, n4);
        n4 = (Ec * INTERc) / 4;
        split_bf16_kernel<<<(n4 + 255)/256, 256>>>(w_out, wohi, wolo, n4);
    }
    // 1) in_proj GEMM: [4096,2048] x [8512,2048]^T
    {
        dim3 grid((PROJc + 127) / 128, ROWSc / 128);
        gemm_mma<<<grid, 256, GEMM_SMEM>>>(xhi, xlo, whi, wlo, proj, ROWSc, PROJc, Ec);
    }
    // 2) depthwise conv + SiLU
    {
        dim3 grid(CONVDc / 256, Bc);
        conv_silu_kernel<<<grid, 256>>>(proj, conv_w, conv_b, xbc);
    }
    // 3) dt softplus + per-chunk cumsum
    {
        dim3 grid(Hc, NCHc, Bc);
        dt_scan_kernel<<<grid, 256>>>(proj, A_log, dt_bias, dtb, acum, suma);
    }
    // 4) local chunk states
    {
        dim3 grid(Hc, NCHc, Bc);
        local_state_kernel<<<grid, 256, LS_SMEM>>>(xbc, dtb, acum, states);
    }
    // 5) Y_diag
    {
        dim3 grid(Hc, NCHc, Bc);
        ydiag_kernel<<<grid, 256, YD_SMEM>>>(xbc, dtb, acum, yb);
    }
    // 6) inter-chunk scan
    {
        dim3 grid(Hc, Bc);
        chunk_scan_kernel<<<grid, 256>>>(suma, states);
    }
    // 7) Y_off + D residual
    {
        dim3 grid(Hc, NCHc, Bc);
        yoff_kernel<<<grid, 256, YO_SMEM>>>(xbc, acum, states, Dv, yb);
    }
    // 8) gate + RMSNorm -> bf16 split
    {
        gatenorm_kernel<<<ROWSc, 256>>>(proj, norm_w, yb, yhi, ylo);
    }
    // 9) out_proj GEMM: [4096,4096] x [2048,4096]^T -> d_out
    {
        dim3 grid(Ec / 128, ROWSc / 128);
        gemm_mma<<<grid, 256, GEMM_SMEM>>>(yhi, ylo, wohi, wolo, out, ROWSc, Ec, INTERc);
    }
}